// round 6
// baseline (speedup 1.0000x reference)
#include <cuda_runtime.h>
#include <cuda_bf16.h>
#include <math.h>
#include <cstdint>

#define D 128
#define MAX_NODES 50000
#define MAX_EDGES 640000
#define MAX_GRAPHS 500
#define BN_EPS 1e-5f

// ---------------- scratch ----------------------------------------------------
__device__ float g_x1  [MAX_NODES * D];
__device__ float g_x2  [MAX_NODES * D];
__device__ float g_pool[MAX_GRAPHS * D];
__device__ float g_w1t [3 * D * D];
__device__ float g_w2t [3 * D * D];
__device__ int   g_cnt [MAX_NODES];
__device__ int   g_rowptr[MAX_NODES + 1];
__device__ int   g_fill[MAX_NODES];
__device__ int   g_csrsrc[MAX_EDGES];

// ---------------- helpers ----------------------------------------------------
__device__ __forceinline__ float tf32r(float v) {
    float o;
    asm("cvt.rna.tf32.f32 %0, %1;" : "=f"(o) : "f"(v));
    return o;
}
__device__ __forceinline__ void red_add_v2(float* p, float a, float b) {
    asm volatile("red.global.add.v2.f32 [%0], {%1,%2};"
                 :: "l"(p), "f"(a), "f"(b) : "memory");
}
__device__ __forceinline__ void mma_tf32(float* d, const uint32_t* a, const uint32_t* b) {
    asm volatile(
        "mma.sync.aligned.m16n8k8.row.col.f32.tf32.tf32.f32 "
        "{%0,%1,%2,%3}, {%4,%5,%6,%7}, {%8,%9}, {%0,%1,%2,%3};"
        : "+f"(d[0]), "+f"(d[1]), "+f"(d[2]), "+f"(d[3])
        : "r"(a[0]), "r"(a[1]), "r"(a[2]), "r"(a[3]), "r"(b[0]), "r"(b[1]));
}

// ---------------- CSR build ---------------------------------------------------
__global__ void hist_kernel(const int* __restrict__ dst, int* __restrict__ cnt, int nEdges) {
    int e = blockIdx.x * blockDim.x + threadIdx.x;
    if (e < nEdges) atomicAdd(&cnt[dst[e]], 1);
}

__global__ void scan_kernel(const int* __restrict__ cnt, int* __restrict__ rowptr,
                            int* __restrict__ fillp, int n) {
    __shared__ int part[1024];
    int tid = threadIdx.x;
    int chunk = (n + 1023) / 1024;
    int beg = tid * chunk;
    int end = beg + chunk < n ? beg + chunk : n;
    int s = 0;
    for (int i = beg; i < end; i++) s += cnt[i];
    part[tid] = s;
    __syncthreads();
    for (int off = 1; off < 1024; off <<= 1) {
        int v = (tid >= off) ? part[tid - off] : 0;
        __syncthreads();
        part[tid] += v;
        __syncthreads();
    }
    int base = (tid > 0) ? part[tid - 1] : 0;
    for (int i = beg; i < end; i++) {
        rowptr[i] = base;
        fillp[i]  = base;
        base += cnt[i];
    }
    if (tid == 1023) rowptr[n] = part[1023];
}

__global__ void fill_kernel(const int* __restrict__ src, const int* __restrict__ dst,
                            int* __restrict__ fillp, int* __restrict__ csrsrc, int nEdges) {
    int e = blockIdx.x * blockDim.x + threadIdx.x;
    if (e < nEdges) {
        int p = atomicAdd(&fillp[dst[e]], 1);
        csrsrc[p] = src[e];
    }
}

// ---------------- weight prep: transpose + tf32 round ------------------------
__global__ void wprep_kernel(const float* __restrict__ W1, const float* __restrict__ W2,
                             float* __restrict__ w1t, float* __restrict__ w2t) {
    __shared__ float tile[32][33];
    int z = blockIdx.z;
    const float* src = (z < 3) ? (W1 + z * D * D) : (W2 + (z - 3) * D * D);
    float*       dstp = (z < 3) ? (w1t + z * D * D) : (w2t + (z - 3) * D * D);
    int x0 = blockIdx.x * 32, y0 = blockIdx.y * 32;
    int tx = threadIdx.x, ty = threadIdx.y;
    #pragma unroll
    for (int j = 0; j < 4; j++)
        tile[ty + j * 8][tx] = src[(y0 + ty + j * 8) * D + x0 + tx];
    __syncthreads();
    #pragma unroll
    for (int j = 0; j < 4; j++)
        dstp[(x0 + ty + j * 8) * D + y0 + tx] = tf32r(tile[tx][ty + j * 8]);
}

// ---------------- fused: gather + MLP (+ optional pool) -----------------------
#define LDS_STRIDE 132
#define TILE_FLOATS (128 * LDS_STRIDE)
#define P_FLOATS (5 * 128)
#define SMEM_TOTAL_MLP ((2 * TILE_FLOATS + P_FLOATS) * 4)

__global__ __launch_bounds__(256, 1)
void mlp_mma_kernel(const float* __restrict__ xin,
                    const int* __restrict__ rowptr,
                    const int* __restrict__ csrsrc,
                    const float* __restrict__ w1t, const float* __restrict__ b1,
                    const float* __restrict__ w2t, const float* __restrict__ b2,
                    const float* __restrict__ bns, const float* __restrict__ bnb,
                    const float* __restrict__ bnm, const float* __restrict__ bnv,
                    float* __restrict__ xout,
                    const int* __restrict__ batch, float* __restrict__ pool,
                    int poolMode, int nNodes) {
    extern __shared__ float smem[];
    float* As  = smem;                    // [128][132]
    float* Bs  = smem + TILE_FLOATS;      // [128][132]
    float* sb1 = smem + 2 * TILE_FLOATS;
    float* sb2 = sb1 + 128;
    float* skk = sb2 + 128;
    float* smm = skk + 128;
    float* scc = smm + 128;

    int tid  = threadIdx.x;
    int wid  = tid >> 5;
    int lane = tid & 31;
    int mg   = wid >> 1;
    int ng   = wid & 1;
    int gp   = lane >> 2;
    int tq   = lane & 3;
    int row0 = blockIdx.x * 128;

    if (tid < 128) {
        sb1[tid] = b1[tid];
        sb2[tid] = b2[tid];
        skk[tid] = bns[tid] * rsqrtf(bnv[tid] + BN_EPS);
        smm[tid] = bnm[tid];
        scc[tid] = bnb[tid];
    }

    const float4* x4 = (const float4*)xin;

    // ---- gather: A row = tf32( x[row] + sum_{e in CSR(row)} x[src] ) --------
    #pragma unroll 1
    for (int rr = 0; rr < 16; rr++) {
        int row = wid * 16 + rr;
        int gr  = row0 + row;
        float4 a0 = make_float4(0.f, 0.f, 0.f, 0.f);
        float4 a1 = make_float4(0.f, 0.f, 0.f, 0.f);
        if (gr < nNodes) {
            a0 = x4[(size_t)gr * 32 + lane];
            int beg = rowptr[gr];
            int end = rowptr[gr + 1];
            int e = beg;
            for (; e + 1 < end; e += 2) {
                int s0 = csrsrc[e];
                int s1 = csrsrc[e + 1];
                float4 v0 = x4[(size_t)s0 * 32 + lane];
                float4 v1 = x4[(size_t)s1 * 32 + lane];
                a0.x += v0.x; a0.y += v0.y; a0.z += v0.z; a0.w += v0.w;
                a1.x += v1.x; a1.y += v1.y; a1.z += v1.z; a1.w += v1.w;
            }
            if (e < end) {
                int s0 = csrsrc[e];
                float4 v0 = x4[(size_t)s0 * 32 + lane];
                a0.x += v0.x; a0.y += v0.y; a0.z += v0.z; a0.w += v0.w;
            }
        }
        float4 hv;
        hv.x = tf32r(a0.x + a1.x);
        hv.y = tf32r(a0.y + a1.y);
        hv.z = tf32r(a0.z + a1.z);
        hv.w = tf32r(a0.w + a1.w);
        *(float4*)(As + row * LDS_STRIDE + lane * 4) = hv;
    }
    // ---- load B (W1T) -------------------------------------------------------
    {
        const float4* w14 = (const float4*)w1t;
        for (int i = tid; i < 128 * 32; i += 256) {
            int row = i >> 5, c4 = i & 31;
            *(float4*)(Bs + row * LDS_STRIDE + c4 * 4) = w14[i];
        }
    }
    __syncthreads();

    float acc[2][8][4];
    #pragma unroll
    for (int mi = 0; mi < 2; mi++)
        #pragma unroll
        for (int ni = 0; ni < 8; ni++)
            #pragma unroll
            for (int c = 0; c < 4; c++) acc[mi][ni][c] = 0.f;

    // ---- GEMM 1: T = H @ W1 -------------------------------------------------
    #pragma unroll
    for (int s = 0; s < 16; s++) {
        int k0 = s * 8;
        uint32_t afr[2][4], bfr[8][2];
        #pragma unroll
        for (int mi = 0; mi < 2; mi++) {
            const float* ap = As + (mg * 32 + mi * 16 + gp) * LDS_STRIDE + k0 + tq;
            afr[mi][0] = __float_as_uint(ap[0]);
            afr[mi][1] = __float_as_uint(ap[8 * LDS_STRIDE]);
            afr[mi][2] = __float_as_uint(ap[4]);
            afr[mi][3] = __float_as_uint(ap[8 * LDS_STRIDE + 4]);
        }
        #pragma unroll
        for (int ni = 0; ni < 8; ni++) {
            const float* bp = Bs + (ng * 64 + ni * 8 + gp) * LDS_STRIDE + k0 + tq;
            bfr[ni][0] = __float_as_uint(bp[0]);
            bfr[ni][1] = __float_as_uint(bp[4]);
        }
        #pragma unroll
        for (int mi = 0; mi < 2; mi++)
            #pragma unroll
            for (int ni = 0; ni < 8; ni++)
                mma_tf32(acc[mi][ni], afr[mi], bfr[ni]);
    }
    __syncthreads();

    // ---- epilogue 1: T = tf32(relu(y + b1)) -> As ---------------------------
    #pragma unroll
    for (int mi = 0; mi < 2; mi++) {
        #pragma unroll
        for (int ni = 0; ni < 8; ni++) {
            int col = ng * 64 + ni * 8 + tq * 2;
            int r0  = mg * 32 + mi * 16 + gp;
            float t0 = acc[mi][ni][0] + sb1[col];
            float t1 = acc[mi][ni][1] + sb1[col + 1];
            float t2 = acc[mi][ni][2] + sb1[col];
            float t3 = acc[mi][ni][3] + sb1[col + 1];
            float2 v01 = make_float2(tf32r(t0 > 0.f ? t0 : 0.f), tf32r(t1 > 0.f ? t1 : 0.f));
            float2 v23 = make_float2(tf32r(t2 > 0.f ? t2 : 0.f), tf32r(t3 > 0.f ? t3 : 0.f));
            *(float2*)(As + r0 * LDS_STRIDE + col)       = v01;
            *(float2*)(As + (r0 + 8) * LDS_STRIDE + col) = v23;
            acc[mi][ni][0] = 0.f; acc[mi][ni][1] = 0.f;
            acc[mi][ni][2] = 0.f; acc[mi][ni][3] = 0.f;
        }
    }
    {
        const float4* w24 = (const float4*)w2t;
        for (int i = tid; i < 128 * 32; i += 256) {
            int row = i >> 5, c4 = i & 31;
            *(float4*)(Bs + row * LDS_STRIDE + c4 * 4) = w24[i];
        }
    }
    __syncthreads();

    // ---- GEMM 2: Y = T @ W2 -------------------------------------------------
    #pragma unroll
    for (int s = 0; s < 16; s++) {
        int k0 = s * 8;
        uint32_t afr[2][4], bfr[8][2];
        #pragma unroll
        for (int mi = 0; mi < 2; mi++) {
            const float* ap = As + (mg * 32 + mi * 16 + gp) * LDS_STRIDE + k0 + tq;
            afr[mi][0] = __float_as_uint(ap[0]);
            afr[mi][1] = __float_as_uint(ap[8 * LDS_STRIDE]);
            afr[mi][2] = __float_as_uint(ap[4]);
            afr[mi][3] = __float_as_uint(ap[8 * LDS_STRIDE + 4]);
        }
        #pragma unroll
        for (int ni = 0; ni < 8; ni++) {
            const float* bp = Bs + (ng * 64 + ni * 8 + gp) * LDS_STRIDE + k0 + tq;
            bfr[ni][0] = __float_as_uint(bp[0]);
            bfr[ni][1] = __float_as_uint(bp[4]);
        }
        #pragma unroll
        for (int mi = 0; mi < 2; mi++)
            #pragma unroll
            for (int ni = 0; ni < 8; ni++)
                mma_tf32(acc[mi][ni], afr[mi], bfr[ni]);
    }

    // ---- epilogue 2: bias + BN + relu -> gmem (or pool via RED) -------------
    #pragma unroll
    for (int mi = 0; mi < 2; mi++) {
        #pragma unroll
        for (int ni = 0; ni < 8; ni++) {
            int col = ng * 64 + ni * 8 + tq * 2;
            int r0  = mg * 32 + mi * 16 + gp;
            int gr0 = row0 + r0;
            int gr1 = gr0 + 8;
            float kk0 = skk[col], kk1 = skk[col + 1];
            float t;
            float2 v;
            if (gr0 < nNodes) {
                t = (acc[mi][ni][0] + sb2[col]     - smm[col])     * kk0 + scc[col];
                v.x = t > 0.f ? t : 0.f;
                t = (acc[mi][ni][1] + sb2[col + 1] - smm[col + 1]) * kk1 + scc[col + 1];
                v.y = t > 0.f ? t : 0.f;
                if (poolMode) red_add_v2(pool + (size_t)batch[gr0] * D + col, v.x, v.y);
                else          *(float2*)(xout + (size_t)gr0 * D + col) = v;
            }
            if (gr1 < nNodes) {
                t = (acc[mi][ni][2] + sb2[col]     - smm[col])     * kk0 + scc[col];
                v.x = t > 0.f ? t : 0.f;
                t = (acc[mi][ni][3] + sb2[col + 1] - smm[col + 1]) * kk1 + scc[col + 1];
                v.y = t > 0.f ? t : 0.f;
                if (poolMode) red_add_v2(pool + (size_t)batch[gr1] * D + col, v.x, v.y);
                else          *(float2*)(xout + (size_t)gr1 * D + col) = v;
            }
        }
    }
}

// ---------------- head --------------------------------------------------------
#define HID 64
#define NCLS 12
__global__ void head_kernel(const float* __restrict__ pool,
                            const float* __restrict__ Wh1, const float* __restrict__ bh1,
                            const float* __restrict__ Wh2, const float* __restrict__ bh2,
                            float* __restrict__ out, int nGraphs) {
    __shared__ float sg[D];
    __shared__ float sh1[HID];
    int g = blockIdx.x;
    if (g >= nGraphs) return;
    int tid = threadIdx.x;  // 64 threads
    sg[tid]       = pool[g * D + tid];
    sg[tid + HID] = pool[g * D + tid + HID];
    __syncthreads();
    float a = bh1[tid];
    #pragma unroll 4
    for (int k = 0; k < D; k++) a += sg[k] * Wh1[k * HID + tid];
    sh1[tid] = a > 0.f ? a : 0.f;
    __syncthreads();
    if (tid < NCLS) {
        float o = bh2[tid];
        #pragma unroll
        for (int k = 0; k < HID; k++) o += sh1[k] * Wh2[k * NCLS + tid];
        out[g * NCLS + tid] = 1.f / (1.f + expf(-o));
    }
}

// ---------------- launcher ---------------------------------------------------
extern "C" void kernel_launch(void* const* d_in, const int* in_sizes, int n_in,
                              void* d_out, int out_size) {
    const float* x     = (const float*)d_in[0];
    const int*   ei    = (const int*)d_in[1];
    const int*   batch = (const int*)d_in[2];
    const float* W1    = (const float*)d_in[3];
    const float* b1    = (const float*)d_in[4];
    const float* W2    = (const float*)d_in[5];
    const float* b2    = (const float*)d_in[6];
    const float* bns   = (const float*)d_in[7];
    const float* bnb   = (const float*)d_in[8];
    const float* bnm   = (const float*)d_in[9];
    const float* bnv   = (const float*)d_in[10];
    const float* Wh1   = (const float*)d_in[11];
    const float* bh1   = (const float*)d_in[12];
    const float* Wh2   = (const float*)d_in[13];
    const float* bh2   = (const float*)d_in[14];
    float* out = (float*)d_out;

    int nNodes  = in_sizes[0] / D;
    int nEdges  = in_sizes[1] / 2;
    int nGraphs = out_size / NCLS;

    const int* src = ei;
    const int* dst = ei + nEdges;

    float *x1, *x2, *pool, *w1t, *w2t;
    int *cnt, *rowptr, *fillp, *csrsrc;
    cudaGetSymbolAddress((void**)&x1,     g_x1);
    cudaGetSymbolAddress((void**)&x2,     g_x2);
    cudaGetSymbolAddress((void**)&pool,   g_pool);
    cudaGetSymbolAddress((void**)&w1t,    g_w1t);
    cudaGetSymbolAddress((void**)&w2t,    g_w2t);
    cudaGetSymbolAddress((void**)&cnt,    g_cnt);
    cudaGetSymbolAddress((void**)&rowptr, g_rowptr);
    cudaGetSymbolAddress((void**)&fillp,  g_fill);
    cudaGetSymbolAddress((void**)&csrsrc, g_csrsrc);

    cudaFuncSetAttribute(mlp_mma_kernel, cudaFuncAttributeMaxDynamicSharedMemorySize,
                         SMEM_TOTAL_MLP);

    // weight prep + CSR build (once per launch)
    wprep_kernel<<<dim3(4, 4, 6), dim3(32, 8)>>>(W1, W2, w1t, w2t);
    cudaMemsetAsync(cnt, 0, (size_t)nNodes * sizeof(int));
    int eb = (nEdges + 255) / 256;
    hist_kernel<<<eb, 256>>>(dst, cnt, nEdges);
    scan_kernel<<<1, 1024>>>(cnt, rowptr, fillp, nNodes);
    fill_kernel<<<eb, 256>>>(src, dst, fillp, csrsrc, nEdges);

    cudaMemsetAsync(pool, 0, (size_t)nGraphs * D * sizeof(float));

    int mlpBlocks = (nNodes + 127) / 128;
    const float* xs[3] = { x, x1, x2 };
    float*       xd[3] = { x1, x2, x1 };

    for (int l = 0; l < 3; l++) {
        mlp_mma_kernel<<<mlpBlocks, 256, SMEM_TOTAL_MLP>>>(
            xs[l], rowptr, csrsrc,
            w1t + l * D * D, b1 + l * D,
            w2t + l * D * D, b2 + l * D,
            bns + l * D, bnb + l * D, bnm + l * D, bnv + l * D,
            xd[l], batch, pool, (l == 2) ? 1 : 0, nNodes);
    }

    head_kernel<<<nGraphs, HID>>>(pool, Wh1, bh1, Wh2, bh2, out, nGraphs);
}

// round 7
// speedup vs baseline: 1.2597x; 1.2597x over previous
#include <cuda_runtime.h>
#include <cuda_bf16.h>
#include <math.h>
#include <cstdint>

#define D 128
#define MAX_NODES 50000
#define MAX_EDGES 640000
#define MAX_GRAPHS 500
#define BN_EPS 1e-5f

// ---------------- scratch ----------------------------------------------------
__device__ float g_h   [MAX_NODES * D];   // gathered + tf32-rounded input tile
__device__ float g_x1  [MAX_NODES * D];
__device__ float g_x2  [MAX_NODES * D];
__device__ float g_pool[MAX_GRAPHS * D];
__device__ float g_w1t [3 * D * D];
__device__ float g_w2t [3 * D * D];
__device__ int   g_cnt [MAX_NODES];
__device__ int   g_rowptr[MAX_NODES + 1];
__device__ int   g_fill[MAX_NODES];
__device__ int   g_csrsrc[MAX_EDGES];

// ---------------- helpers ----------------------------------------------------
__device__ __forceinline__ float tf32r(float v) {
    float o;
    asm("cvt.rna.tf32.f32 %0, %1;" : "=f"(o) : "f"(v));
    return o;
}
__device__ __forceinline__ void red_add_v2(float* p, float a, float b) {
    asm volatile("red.global.add.v2.f32 [%0], {%1,%2};"
                 :: "l"(p), "f"(a), "f"(b) : "memory");
}
__device__ __forceinline__ void mma_tf32(float* d, const uint32_t* a, const uint32_t* b) {
    asm volatile(
        "mma.sync.aligned.m16n8k8.row.col.f32.tf32.tf32.f32 "
        "{%0,%1,%2,%3}, {%4,%5,%6,%7}, {%8,%9}, {%0,%1,%2,%3};"
        : "+f"(d[0]), "+f"(d[1]), "+f"(d[2]), "+f"(d[3])
        : "r"(a[0]), "r"(a[1]), "r"(a[2]), "r"(a[3]), "r"(b[0]), "r"(b[1]));
}

// ---------------- CSR build ---------------------------------------------------
__global__ void hist_kernel(const int* __restrict__ dst, int* __restrict__ cnt, int nEdges) {
    int e = blockIdx.x * blockDim.x + threadIdx.x;
    if (e < nEdges) atomicAdd(&cnt[dst[e]], 1);
}

__global__ void scan_kernel(const int* __restrict__ cnt, int* __restrict__ rowptr,
                            int* __restrict__ fillp, int n) {
    __shared__ int part[1024];
    int tid = threadIdx.x;
    int chunk = (n + 1023) / 1024;
    int beg = tid * chunk;
    int end = beg + chunk < n ? beg + chunk : n;
    int s = 0;
    for (int i = beg; i < end; i++) s += cnt[i];
    part[tid] = s;
    __syncthreads();
    for (int off = 1; off < 1024; off <<= 1) {
        int v = (tid >= off) ? part[tid - off] : 0;
        __syncthreads();
        part[tid] += v;
        __syncthreads();
    }
    int base = (tid > 0) ? part[tid - 1] : 0;
    for (int i = beg; i < end; i++) {
        rowptr[i] = base;
        fillp[i]  = base;
        base += cnt[i];
    }
    if (tid == 1023) rowptr[n] = part[1023];
}

__global__ void fill_kernel(const int* __restrict__ src, const int* __restrict__ dst,
                            int* __restrict__ fillp, int* __restrict__ csrsrc, int nEdges) {
    int e = blockIdx.x * blockDim.x + threadIdx.x;
    if (e < nEdges) {
        int p = atomicAdd(&fillp[dst[e]], 1);
        csrsrc[p] = src[e];
    }
}

// ---------------- weight prep: transpose + tf32 round ------------------------
__global__ void wprep_kernel(const float* __restrict__ W1, const float* __restrict__ W2,
                             float* __restrict__ w1t, float* __restrict__ w2t) {
    __shared__ float tile[32][33];
    int z = blockIdx.z;
    const float* src = (z < 3) ? (W1 + z * D * D) : (W2 + (z - 3) * D * D);
    float*       dstp = (z < 3) ? (w1t + z * D * D) : (w2t + (z - 3) * D * D);
    int x0 = blockIdx.x * 32, y0 = blockIdx.y * 32;
    int tx = threadIdx.x, ty = threadIdx.y;
    #pragma unroll
    for (int j = 0; j < 4; j++)
        tile[ty + j * 8][tx] = src[(y0 + ty + j * 8) * D + x0 + tx];
    __syncthreads();
    #pragma unroll
    for (int j = 0; j < 4; j++)
        dstp[(x0 + ty + j * 8) * D + y0 + tx] = tf32r(tile[tx][ty + j * 8]);
}

// ---------------- gather: h[i] = tf32r( x[i] + sum_{e in CSR(i)} x[src] ) -----
// one warp per node, high occupancy, 4-way unrolled for MLP
__global__ __launch_bounds__(256)
void gather_kernel(const float* __restrict__ x,
                   const int* __restrict__ rowptr,
                   const int* __restrict__ csrsrc,
                   float* __restrict__ h, int nNodes) {
    int gid  = blockIdx.x * blockDim.x + threadIdx.x;
    int node = gid >> 5;
    int lane = gid & 31;
    if (node >= nNodes) return;
    const float4* x4 = (const float4*)x;
    float4 a0 = x4[(size_t)node * 32 + lane];
    float4 a1 = make_float4(0.f, 0.f, 0.f, 0.f);
    float4 a2 = make_float4(0.f, 0.f, 0.f, 0.f);
    float4 a3 = make_float4(0.f, 0.f, 0.f, 0.f);
    int beg = rowptr[node];
    int end = rowptr[node + 1];
    int e = beg;
    for (; e + 3 < end; e += 4) {
        int s0 = csrsrc[e], s1 = csrsrc[e + 1], s2 = csrsrc[e + 2], s3 = csrsrc[e + 3];
        float4 v0 = x4[(size_t)s0 * 32 + lane];
        float4 v1 = x4[(size_t)s1 * 32 + lane];
        float4 v2 = x4[(size_t)s2 * 32 + lane];
        float4 v3 = x4[(size_t)s3 * 32 + lane];
        a0.x += v0.x; a0.y += v0.y; a0.z += v0.z; a0.w += v0.w;
        a1.x += v1.x; a1.y += v1.y; a1.z += v1.z; a1.w += v1.w;
        a2.x += v2.x; a2.y += v2.y; a2.z += v2.z; a2.w += v2.w;
        a3.x += v3.x; a3.y += v3.y; a3.z += v3.z; a3.w += v3.w;
    }
    for (; e < end; e++) {
        int s0 = csrsrc[e];
        float4 v0 = x4[(size_t)s0 * 32 + lane];
        a0.x += v0.x; a0.y += v0.y; a0.z += v0.z; a0.w += v0.w;
    }
    float4 hv;
    hv.x = tf32r((a0.x + a1.x) + (a2.x + a3.x));
    hv.y = tf32r((a0.y + a1.y) + (a2.y + a3.y));
    hv.z = tf32r((a0.z + a1.z) + (a2.z + a3.z));
    hv.w = tf32r((a0.w + a1.w) + (a2.w + a3.w));
    ((float4*)h)[(size_t)node * 32 + lane] = hv;
}

// ---------------- fused MLP layer on mma.sync tf32 ----------------------------
#define LDS_STRIDE 132
#define TILE_FLOATS (128 * LDS_STRIDE)
#define P_FLOATS (5 * 128)
#define SMEM_TOTAL_MLP ((2 * TILE_FLOATS + P_FLOATS) * 4)

__global__ __launch_bounds__(256, 1)
void mlp_mma_kernel(const float* __restrict__ hin,
                    const float* __restrict__ w1t, const float* __restrict__ b1,
                    const float* __restrict__ w2t, const float* __restrict__ b2,
                    const float* __restrict__ bns, const float* __restrict__ bnb,
                    const float* __restrict__ bnm, const float* __restrict__ bnv,
                    float* __restrict__ xout,
                    const int* __restrict__ batch, float* __restrict__ pool,
                    int poolMode, int nNodes) {
    extern __shared__ float smem[];
    float* As  = smem;                    // [128][132]
    float* Bs  = smem + TILE_FLOATS;      // [128][132]
    float* sb1 = smem + 2 * TILE_FLOATS;
    float* sb2 = sb1 + 128;
    float* skk = sb2 + 128;
    float* smm = skk + 128;
    float* scc = smm + 128;

    int tid  = threadIdx.x;
    int wid  = tid >> 5;
    int lane = tid & 31;
    int mg   = wid >> 1;
    int ng   = wid & 1;
    int gp   = lane >> 2;
    int tq   = lane & 3;
    int row0 = blockIdx.x * 128;

    if (tid < 128) {
        sb1[tid] = b1[tid];
        sb2[tid] = b2[tid];
        skk[tid] = bns[tid] * rsqrtf(bnv[tid] + BN_EPS);
        smm[tid] = bnm[tid];
        scc[tid] = bnb[tid];
    }

    // ---- load A (pre-gathered, pre-rounded h) and B (W1T) -------------------
    const float4* h4  = (const float4*)hin;
    const float4* w14 = (const float4*)w1t;
    for (int i = tid; i < 128 * 32; i += 256) {
        int row = i >> 5, c4 = i & 31;
        int gr = row0 + row;
        float4 hv = make_float4(0.f, 0.f, 0.f, 0.f);
        if (gr < nNodes) hv = h4[(size_t)gr * 32 + c4];
        *(float4*)(As + row * LDS_STRIDE + c4 * 4) = hv;
        *(float4*)(Bs + row * LDS_STRIDE + c4 * 4) = w14[i];
    }
    __syncthreads();

    float acc[2][8][4];
    #pragma unroll
    for (int mi = 0; mi < 2; mi++)
        #pragma unroll
        for (int ni = 0; ni < 8; ni++)
            #pragma unroll
            for (int c = 0; c < 4; c++) acc[mi][ni][c] = 0.f;

    // ---- GEMM 1: T = H @ W1 -------------------------------------------------
    #pragma unroll
    for (int s = 0; s < 16; s++) {
        int k0 = s * 8;
        uint32_t afr[2][4], bfr[8][2];
        #pragma unroll
        for (int mi = 0; mi < 2; mi++) {
            const float* ap = As + (mg * 32 + mi * 16 + gp) * LDS_STRIDE + k0 + tq;
            afr[mi][0] = __float_as_uint(ap[0]);
            afr[mi][1] = __float_as_uint(ap[8 * LDS_STRIDE]);
            afr[mi][2] = __float_as_uint(ap[4]);
            afr[mi][3] = __float_as_uint(ap[8 * LDS_STRIDE + 4]);
        }
        #pragma unroll
        for (int ni = 0; ni < 8; ni++) {
            const float* bp = Bs + (ng * 64 + ni * 8 + gp) * LDS_STRIDE + k0 + tq;
            bfr[ni][0] = __float_as_uint(bp[0]);
            bfr[ni][1] = __float_as_uint(bp[4]);
        }
        #pragma unroll
        for (int mi = 0; mi < 2; mi++)
            #pragma unroll
            for (int ni = 0; ni < 8; ni++)
                mma_tf32(acc[mi][ni], afr[mi], bfr[ni]);
    }
    __syncthreads();

    // ---- epilogue 1: T = tf32(relu(y + b1)) -> As ---------------------------
    #pragma unroll
    for (int mi = 0; mi < 2; mi++) {
        #pragma unroll
        for (int ni = 0; ni < 8; ni++) {
            int col = ng * 64 + ni * 8 + tq * 2;
            int r0  = mg * 32 + mi * 16 + gp;
            float t0 = acc[mi][ni][0] + sb1[col];
            float t1 = acc[mi][ni][1] + sb1[col + 1];
            float t2 = acc[mi][ni][2] + sb1[col];
            float t3 = acc[mi][ni][3] + sb1[col + 1];
            float2 v01 = make_float2(tf32r(t0 > 0.f ? t0 : 0.f), tf32r(t1 > 0.f ? t1 : 0.f));
            float2 v23 = make_float2(tf32r(t2 > 0.f ? t2 : 0.f), tf32r(t3 > 0.f ? t3 : 0.f));
            *(float2*)(As + r0 * LDS_STRIDE + col)       = v01;
            *(float2*)(As + (r0 + 8) * LDS_STRIDE + col) = v23;
            acc[mi][ni][0] = 0.f; acc[mi][ni][1] = 0.f;
            acc[mi][ni][2] = 0.f; acc[mi][ni][3] = 0.f;
        }
    }
    {
        const float4* w24 = (const float4*)w2t;
        for (int i = tid; i < 128 * 32; i += 256) {
            int row = i >> 5, c4 = i & 31;
            *(float4*)(Bs + row * LDS_STRIDE + c4 * 4) = w24[i];
        }
    }
    __syncthreads();

    // ---- GEMM 2: Y = T @ W2 -------------------------------------------------
    #pragma unroll
    for (int s = 0; s < 16; s++) {
        int k0 = s * 8;
        uint32_t afr[2][4], bfr[8][2];
        #pragma unroll
        for (int mi = 0; mi < 2; mi++) {
            const float* ap = As + (mg * 32 + mi * 16 + gp) * LDS_STRIDE + k0 + tq;
            afr[mi][0] = __float_as_uint(ap[0]);
            afr[mi][1] = __float_as_uint(ap[8 * LDS_STRIDE]);
            afr[mi][2] = __float_as_uint(ap[4]);
            afr[mi][3] = __float_as_uint(ap[8 * LDS_STRIDE + 4]);
        }
        #pragma unroll
        for (int ni = 0; ni < 8; ni++) {
            const float* bp = Bs + (ng * 64 + ni * 8 + gp) * LDS_STRIDE + k0 + tq;
            bfr[ni][0] = __float_as_uint(bp[0]);
            bfr[ni][1] = __float_as_uint(bp[4]);
        }
        #pragma unroll
        for (int mi = 0; mi < 2; mi++)
            #pragma unroll
            for (int ni = 0; ni < 8; ni++)
                mma_tf32(acc[mi][ni], afr[mi], bfr[ni]);
    }

    // ---- epilogue 2: bias + BN + relu -> gmem (or pool via RED) -------------
    #pragma unroll
    for (int mi = 0; mi < 2; mi++) {
        #pragma unroll
        for (int ni = 0; ni < 8; ni++) {
            int col = ng * 64 + ni * 8 + tq * 2;
            int r0  = mg * 32 + mi * 16 + gp;
            int gr0 = row0 + r0;
            int gr1 = gr0 + 8;
            float kk0 = skk[col], kk1 = skk[col + 1];
            float t;
            float2 v;
            if (gr0 < nNodes) {
                t = (acc[mi][ni][0] + sb2[col]     - smm[col])     * kk0 + scc[col];
                v.x = t > 0.f ? t : 0.f;
                t = (acc[mi][ni][1] + sb2[col + 1] - smm[col + 1]) * kk1 + scc[col + 1];
                v.y = t > 0.f ? t : 0.f;
                if (poolMode) red_add_v2(pool + (size_t)batch[gr0] * D + col, v.x, v.y);
                else          *(float2*)(xout + (size_t)gr0 * D + col) = v;
            }
            if (gr1 < nNodes) {
                t = (acc[mi][ni][2] + sb2[col]     - smm[col])     * kk0 + scc[col];
                v.x = t > 0.f ? t : 0.f;
                t = (acc[mi][ni][3] + sb2[col + 1] - smm[col + 1]) * kk1 + scc[col + 1];
                v.y = t > 0.f ? t : 0.f;
                if (poolMode) red_add_v2(pool + (size_t)batch[gr1] * D + col, v.x, v.y);
                else          *(float2*)(xout + (size_t)gr1 * D + col) = v;
            }
        }
    }
}

// ---------------- head --------------------------------------------------------
#define HID 64
#define NCLS 12
__global__ void head_kernel(const float* __restrict__ pool,
                            const float* __restrict__ Wh1, const float* __restrict__ bh1,
                            const float* __restrict__ Wh2, const float* __restrict__ bh2,
                            float* __restrict__ out, int nGraphs) {
    __shared__ float sg[D];
    __shared__ float sh1[HID];
    int g = blockIdx.x;
    if (g >= nGraphs) return;
    int tid = threadIdx.x;  // 64 threads
    sg[tid]       = pool[g * D + tid];
    sg[tid + HID] = pool[g * D + tid + HID];
    __syncthreads();
    float a = bh1[tid];
    #pragma unroll 4
    for (int k = 0; k < D; k++) a += sg[k] * Wh1[k * HID + tid];
    sh1[tid] = a > 0.f ? a : 0.f;
    __syncthreads();
    if (tid < NCLS) {
        float o = bh2[tid];
        #pragma unroll
        for (int k = 0; k < HID; k++) o += sh1[k] * Wh2[k * NCLS + tid];
        out[g * NCLS + tid] = 1.f / (1.f + expf(-o));
    }
}

// ---------------- launcher ---------------------------------------------------
extern "C" void kernel_launch(void* const* d_in, const int* in_sizes, int n_in,
                              void* d_out, int out_size) {
    const float* x     = (const float*)d_in[0];
    const int*   ei    = (const int*)d_in[1];
    const int*   batch = (const int*)d_in[2];
    const float* W1    = (const float*)d_in[3];
    const float* b1    = (const float*)d_in[4];
    const float* W2    = (const float*)d_in[5];
    const float* b2    = (const float*)d_in[6];
    const float* bns   = (const float*)d_in[7];
    const float* bnb   = (const float*)d_in[8];
    const float* bnm   = (const float*)d_in[9];
    const float* bnv   = (const float*)d_in[10];
    const float* Wh1   = (const float*)d_in[11];
    const float* bh1   = (const float*)d_in[12];
    const float* Wh2   = (const float*)d_in[13];
    const float* bh2   = (const float*)d_in[14];
    float* out = (float*)d_out;

    int nNodes  = in_sizes[0] / D;
    int nEdges  = in_sizes[1] / 2;
    int nGraphs = out_size / NCLS;

    const int* src = ei;
    const int* dst = ei + nEdges;

    float *h, *x1, *x2, *pool, *w1t, *w2t;
    int *cnt, *rowptr, *fillp, *csrsrc;
    cudaGetSymbolAddress((void**)&h,      g_h);
    cudaGetSymbolAddress((void**)&x1,     g_x1);
    cudaGetSymbolAddress((void**)&x2,     g_x2);
    cudaGetSymbolAddress((void**)&pool,   g_pool);
    cudaGetSymbolAddress((void**)&w1t,    g_w1t);
    cudaGetSymbolAddress((void**)&w2t,    g_w2t);
    cudaGetSymbolAddress((void**)&cnt,    g_cnt);
    cudaGetSymbolAddress((void**)&rowptr, g_rowptr);
    cudaGetSymbolAddress((void**)&fillp,  g_fill);
    cudaGetSymbolAddress((void**)&csrsrc, g_csrsrc);

    cudaFuncSetAttribute(mlp_mma_kernel, cudaFuncAttributeMaxDynamicSharedMemorySize,
                         SMEM_TOTAL_MLP);

    // weight prep + CSR build (once per launch)
    wprep_kernel<<<dim3(4, 4, 6), dim3(32, 8)>>>(W1, W2, w1t, w2t);
    cudaMemsetAsync(cnt, 0, (size_t)nNodes * sizeof(int));
    int eb = (nEdges + 255) / 256;
    hist_kernel<<<eb, 256>>>(dst, cnt, nEdges);
    scan_kernel<<<1, 1024>>>(cnt, rowptr, fillp, nNodes);
    fill_kernel<<<eb, 256>>>(src, dst, fillp, csrsrc, nEdges);

    cudaMemsetAsync(pool, 0, (size_t)nGraphs * D * sizeof(float));

    int mlpBlocks    = (nNodes + 127) / 128;
    int gatherBlocks = (nNodes * 32 + 255) / 256;
    const float* xs[3] = { x, x1, x2 };
    float*       xd[3] = { x1, x2, x1 };

    for (int l = 0; l < 3; l++) {
        gather_kernel<<<gatherBlocks, 256>>>(xs[l], rowptr, csrsrc, h, nNodes);
        mlp_mma_kernel<<<mlpBlocks, 256, SMEM_TOTAL_MLP>>>(
            h,
            w1t + l * D * D, b1 + l * D,
            w2t + l * D * D, b2 + l * D,
            bns + l * D, bnb + l * D, bnm + l * D, bnv + l * D,
            xd[l], batch, pool, (l == 2) ? 1 : 0, nNodes);
    }

    head_kernel<<<nGraphs, HID>>>(pool, Wh1, bh1, Wh2, bh2, out, nGraphs);
}

// round 9
// speedup vs baseline: 1.6129x; 1.2804x over previous
#include <cuda_runtime.h>
#include <cuda_bf16.h>
#include <math.h>
#include <cstdint>

#define D 128
#define MAX_NODES 50000
#define MAX_EDGES 640000
#define MAX_GRAPHS 500
#define BN_EPS 1e-5f

// ---------------- scratch ----------------------------------------------------
__device__ float g_h   [MAX_NODES * D];
__device__ float g_x1  [MAX_NODES * D];
__device__ float g_x2  [MAX_NODES * D];
__device__ float g_pool[MAX_GRAPHS * D];
__device__ float g_w1t [3 * D * D];
__device__ float g_w2t [3 * D * D];
__device__ int   g_cnt [MAX_NODES];
__device__ int   g_rowptr[MAX_NODES + 1];
__device__ int   g_tick[MAX_EDGES];
__device__ int   g_csrsrc[MAX_EDGES];

// ---------------- helpers ----------------------------------------------------
__device__ __forceinline__ float tf32r(float v) {
    float o;
    asm("cvt.rna.tf32.f32 %0, %1;" : "=f"(o) : "f"(v));
    return o;
}
__device__ __forceinline__ void red_add_v2(float* p, float a, float b) {
    asm volatile("red.global.add.v2.f32 [%0], {%1,%2};"
                 :: "l"(p), "f"(a), "f"(b) : "memory");
}
__device__ __forceinline__ void mma_tf32(float* d, const uint32_t* a, const uint32_t* b) {
    asm volatile(
        "mma.sync.aligned.m16n8k8.row.col.f32.tf32.tf32.f32 "
        "{%0,%1,%2,%3}, {%4,%5,%6,%7}, {%8,%9}, {%0,%1,%2,%3};"
        : "+f"(d[0]), "+f"(d[1]), "+f"(d[2]), "+f"(d[3])
        : "r"(a[0]), "r"(a[1]), "r"(a[2]), "r"(a[3]), "r"(b[0]), "r"(b[1]));
}

// ---------------- CSR build ---------------------------------------------------
// pass 1: histogram + per-edge ticket
__global__ void hist_kernel(const int* __restrict__ dst, int* __restrict__ cnt,
                            int* __restrict__ tick, int nEdges) {
    int e = blockIdx.x * blockDim.x + threadIdx.x;
    if (e < nEdges) tick[e] = atomicAdd(&cnt[dst[e]], 1);
}

__global__ void scan_kernel(const int* __restrict__ cnt, int* __restrict__ rowptr, int n) {
    __shared__ int part[1024];
    int tid = threadIdx.x;
    int chunk = (n + 1023) / 1024;
    int beg = tid * chunk;
    int end = beg + chunk < n ? beg + chunk : n;
    int s = 0;
    for (int i = beg; i < end; i++) s += cnt[i];
    part[tid] = s;
    __syncthreads();
    for (int off = 1; off < 1024; off <<= 1) {
        int v = (tid >= off) ? part[tid - off] : 0;
        __syncthreads();
        part[tid] += v;
        __syncthreads();
    }
    int base = (tid > 0) ? part[tid - 1] : 0;
    for (int i = beg; i < end; i++) {
        rowptr[i] = base;
        base += cnt[i];
    }
    if (tid == 1023) rowptr[n] = part[1023];
}

// pass 2: atomic-free scatter using tickets
__global__ void fill_kernel(const int* __restrict__ src, const int* __restrict__ dst,
                            const int* __restrict__ rowptr, const int* __restrict__ tick,
                            int* __restrict__ csrsrc, int nEdges) {
    int e = blockIdx.x * blockDim.x + threadIdx.x;
    if (e < nEdges) csrsrc[rowptr[dst[e]] + tick[e]] = src[e];
}

// ---------------- weight prep: transpose + tf32 round ------------------------
__global__ void wprep_kernel(const float* __restrict__ W1, const float* __restrict__ W2,
                             float* __restrict__ w1t, float* __restrict__ w2t) {
    __shared__ float tile[32][33];
    int z = blockIdx.z;
    const float* src = (z < 3) ? (W1 + z * D * D) : (W2 + (z - 3) * D * D);
    float*       dstp = (z < 3) ? (w1t + z * D * D) : (w2t + (z - 3) * D * D);
    int x0 = blockIdx.x * 32, y0 = blockIdx.y * 32;
    int tx = threadIdx.x, ty = threadIdx.y;
    #pragma unroll
    for (int j = 0; j < 4; j++)
        tile[ty + j * 8][tx] = src[(y0 + ty + j * 8) * D + x0 + tx];
    __syncthreads();
    #pragma unroll
    for (int j = 0; j < 4; j++)
        dstp[(x0 + ty + j * 8) * D + y0 + tx] = tf32r(tile[tx][ty + j * 8]);
}

// ---------------- gather: h[i] = tf32r( x[i] + sum_{e in CSR(i)} x[src] ) -----
__global__ __launch_bounds__(256)
void gather_kernel(const float* __restrict__ x,
                   const int* __restrict__ rowptr,
                   const int* __restrict__ csrsrc,
                   float* __restrict__ h, int nNodes) {
    int gid  = blockIdx.x * blockDim.x + threadIdx.x;
    int node = gid >> 5;
    int lane = gid & 31;
    if (node >= nNodes) return;
    const float4* x4 = (const float4*)x;
    float4 a0 = x4[(size_t)node * 32 + lane];
    float4 a1 = make_float4(0.f, 0.f, 0.f, 0.f);
    float4 a2 = make_float4(0.f, 0.f, 0.f, 0.f);
    float4 a3 = make_float4(0.f, 0.f, 0.f, 0.f);
    int beg = rowptr[node];
    int end = rowptr[node + 1];
    int e = beg;
    for (; e + 3 < end; e += 4) {
        int s0 = csrsrc[e], s1 = csrsrc[e + 1], s2 = csrsrc[e + 2], s3 = csrsrc[e + 3];
        float4 v0 = x4[(size_t)s0 * 32 + lane];
        float4 v1 = x4[(size_t)s1 * 32 + lane];
        float4 v2 = x4[(size_t)s2 * 32 + lane];
        float4 v3 = x4[(size_t)s3 * 32 + lane];
        a0.x += v0.x; a0.y += v0.y; a0.z += v0.z; a0.w += v0.w;
        a1.x += v1.x; a1.y += v1.y; a1.z += v1.z; a1.w += v1.w;
        a2.x += v2.x; a2.y += v2.y; a2.z += v2.z; a2.w += v2.w;
        a3.x += v3.x; a3.y += v3.y; a3.z += v3.z; a3.w += v3.w;
    }
    for (; e < end; e++) {
        int s0 = csrsrc[e];
        float4 v0 = x4[(size_t)s0 * 32 + lane];
        a0.x += v0.x; a0.y += v0.y; a0.z += v0.z; a0.w += v0.w;
    }
    float4 hv;
    hv.x = tf32r((a0.x + a1.x) + (a2.x + a3.x));
    hv.y = tf32r((a0.y + a1.y) + (a2.y + a3.y));
    hv.z = tf32r((a0.z + a1.z) + (a2.z + a3.z));
    hv.w = tf32r((a0.w + a1.w) + (a2.w + a3.w));
    ((float4*)h)[(size_t)node * 32 + lane] = hv;
}

// ---------------- fused MLP layer, TILE_M=64, 2 CTAs/SM -----------------------
#define TILE_M 64
#define LDS_STRIDE 132
#define A_FLOATS (TILE_M * LDS_STRIDE)          // 8448
#define B_FLOATS (128 * LDS_STRIDE)             // 16896
#define P_FLOATS (5 * 128)
#define SMEM_TOTAL_MLP ((A_FLOATS + B_FLOATS + P_FLOATS) * 4)   // ~104 KB

__global__ __launch_bounds__(256, 2)
void mlp_mma_kernel(const float* __restrict__ hin,
                    const float* __restrict__ w1t, const float* __restrict__ b1,
                    const float* __restrict__ w2t, const float* __restrict__ b2,
                    const float* __restrict__ bns, const float* __restrict__ bnb,
                    const float* __restrict__ bnm, const float* __restrict__ bnv,
                    float* __restrict__ xout,
                    const int* __restrict__ batch, float* __restrict__ pool,
                    int poolMode, int nNodes) {
    extern __shared__ float smem[];
    float* As  = smem;                    // [64][132]
    float* Bs  = smem + A_FLOATS;         // [128][132]
    float* sb1 = smem + A_FLOATS + B_FLOATS;
    float* sb2 = sb1 + 128;
    float* skk = sb2 + 128;
    float* smm = skk + 128;
    float* scc = smm + 128;

    int tid  = threadIdx.x;
    int wid  = tid >> 5;
    int lane = tid & 31;
    int mg   = wid >> 2;        // 0..1  (rows mg*32 .. +31)
    int ng   = wid & 3;         // 0..3  (cols ng*32 .. +31)
    int gp   = lane >> 2;       // 0..7
    int tq   = lane & 3;        // 0..3
    int row0 = blockIdx.x * TILE_M;

    if (tid < 128) {
        sb1[tid] = b1[tid];
        sb2[tid] = b2[tid];
        skk[tid] = bns[tid] * rsqrtf(bnv[tid] + BN_EPS);
        smm[tid] = bnm[tid];
        scc[tid] = bnb[tid];
    }

    // ---- load A (pre-gathered h rows) and B (W1T) ---------------------------
    const float4* h4  = (const float4*)hin;
    const float4* w14 = (const float4*)w1t;
    #pragma unroll
    for (int it = 0; it < 8; it++) {
        int i = tid + it * 256;             // TILE_M*32 = 2048 items
        int row = i >> 5, c4 = i & 31;
        int gr = row0 + row;
        float4 hv = make_float4(0.f, 0.f, 0.f, 0.f);
        if (gr < nNodes) hv = h4[(size_t)gr * 32 + c4];
        *(float4*)(As + row * LDS_STRIDE + c4 * 4) = hv;
    }
    #pragma unroll
    for (int it = 0; it < 16; it++) {
        int i = tid + it * 256;             // 128*32 = 4096 items
        int row = i >> 5, c4 = i & 31;
        *(float4*)(Bs + row * LDS_STRIDE + c4 * 4) = w14[i];
    }
    __syncthreads();

    float acc[2][4][4];
    #pragma unroll
    for (int mi = 0; mi < 2; mi++)
        #pragma unroll
        for (int ni = 0; ni < 4; ni++)
            #pragma unroll
            for (int c = 0; c < 4; c++) acc[mi][ni][c] = 0.f;

    // ---- GEMM 1: T = H @ W1 -------------------------------------------------
    #pragma unroll
    for (int s = 0; s < 16; s++) {
        int k0 = s * 8;
        uint32_t afr[2][4], bfr[4][2];
        #pragma unroll
        for (int mi = 0; mi < 2; mi++) {
            const float* ap = As + (mg * 32 + mi * 16 + gp) * LDS_STRIDE + k0 + tq;
            afr[mi][0] = __float_as_uint(ap[0]);
            afr[mi][1] = __float_as_uint(ap[8 * LDS_STRIDE]);
            afr[mi][2] = __float_as_uint(ap[4]);
            afr[mi][3] = __float_as_uint(ap[8 * LDS_STRIDE + 4]);
        }
        #pragma unroll
        for (int ni = 0; ni < 4; ni++) {
            const float* bp = Bs + (ng * 32 + ni * 8 + gp) * LDS_STRIDE + k0 + tq;
            bfr[ni][0] = __float_as_uint(bp[0]);
            bfr[ni][1] = __float_as_uint(bp[4]);
        }
        #pragma unroll
        for (int mi = 0; mi < 2; mi++)
            #pragma unroll
            for (int ni = 0; ni < 4; ni++)
                mma_tf32(acc[mi][ni], afr[mi], bfr[ni]);
    }
    __syncthreads();

    // ---- epilogue 1: T = tf32(relu(y + b1)) -> As ---------------------------
    #pragma unroll
    for (int mi = 0; mi < 2; mi++) {
        #pragma unroll
        for (int ni = 0; ni < 4; ni++) {
            int col = ng * 32 + ni * 8 + tq * 2;
            int r0  = mg * 32 + mi * 16 + gp;
            float t0 = acc[mi][ni][0] + sb1[col];
            float t1 = acc[mi][ni][1] + sb1[col + 1];
            float t2 = acc[mi][ni][2] + sb1[col];
            float t3 = acc[mi][ni][3] + sb1[col + 1];
            float2 v01 = make_float2(tf32r(t0 > 0.f ? t0 : 0.f), tf32r(t1 > 0.f ? t1 : 0.f));
            float2 v23 = make_float2(tf32r(t2 > 0.f ? t2 : 0.f), tf32r(t3 > 0.f ? t3 : 0.f));
            *(float2*)(As + r0 * LDS_STRIDE + col)       = v01;
            *(float2*)(As + (r0 + 8) * LDS_STRIDE + col) = v23;
            acc[mi][ni][0] = 0.f; acc[mi][ni][1] = 0.f;
            acc[mi][ni][2] = 0.f; acc[mi][ni][3] = 0.f;
        }
    }
    {
        const float4* w24 = (const float4*)w2t;
        #pragma unroll
        for (int it = 0; it < 16; it++) {
            int i = tid + it * 256;
            int row = i >> 5, c4 = i & 31;
            *(float4*)(Bs + row * LDS_STRIDE + c4 * 4) = w24[i];
        }
    }
    __syncthreads();

    // ---- GEMM 2: Y = T @ W2 -------------------------------------------------
    #pragma unroll
    for (int s = 0; s < 16; s++) {
        int k0 = s * 8;
        uint32_t afr[2][4], bfr[4][2];
        #pragma unroll
        for (int mi = 0; mi < 2; mi++) {
            const float* ap = As + (mg * 32 + mi * 16 + gp) * LDS_STRIDE + k0 + tq;
            afr[mi][0] = __float_as_uint(ap[0]);
            afr[mi][1] = __float_as_uint(ap[8 * LDS_STRIDE]);
            afr[mi][2] = __float_as_uint(ap[4]);
            afr[mi][3] = __float_as_uint(ap[8 * LDS_STRIDE + 4]);
        }
        #pragma unroll
        for (int ni = 0; ni < 4; ni++) {
            const float* bp = Bs + (ng * 32 + ni * 8 + gp) * LDS_STRIDE + k0 + tq;
            bfr[ni][0] = __float_as_uint(bp[0]);
            bfr[ni][1] = __float_as_uint(bp[4]);
        }
        #pragma unroll
        for (int mi = 0; mi < 2; mi++)
            #pragma unroll
            for (int ni = 0; ni < 4; ni++)
                mma_tf32(acc[mi][ni], afr[mi], bfr[ni]);
    }

    // ---- epilogue 2: bias + BN + relu -> gmem (or pool via RED) -------------
    #pragma unroll
    for (int mi = 0; mi < 2; mi++) {
        #pragma unroll
        for (int ni = 0; ni < 4; ni++) {
            int col = ng * 32 + ni * 8 + tq * 2;
            int r0  = mg * 32 + mi * 16 + gp;
            int gr0 = row0 + r0;
            int gr1 = gr0 + 8;
            float kk0 = skk[col], kk1 = skk[col + 1];
            float t;
            float2 v;
            if (gr0 < nNodes) {
                t = (acc[mi][ni][0] + sb2[col]     - smm[col])     * kk0 + scc[col];
                v.x = t > 0.f ? t : 0.f;
                t = (acc[mi][ni][1] + sb2[col + 1] - smm[col + 1]) * kk1 + scc[col + 1];
                v.y = t > 0.f ? t : 0.f;
                if (poolMode) red_add_v2(pool + (size_t)batch[gr0] * D + col, v.x, v.y);
                else          *(float2*)(xout + (size_t)gr0 * D + col) = v;
            }
            if (gr1 < nNodes) {
                t = (acc[mi][ni][2] + sb2[col]     - smm[col])     * kk0 + scc[col];
                v.x = t > 0.f ? t : 0.f;
                t = (acc[mi][ni][3] + sb2[col + 1] - smm[col + 1]) * kk1 + scc[col + 1];
                v.y = t > 0.f ? t : 0.f;
                if (poolMode) red_add_v2(pool + (size_t)batch[gr1] * D + col, v.x, v.y);
                else          *(float2*)(xout + (size_t)gr1 * D + col) = v;
            }
        }
    }
}

// ---------------- head --------------------------------------------------------
#define HID 64
#define NCLS 12
__global__ void head_kernel(const float* __restrict__ pool,
                            const float* __restrict__ Wh1, const float* __restrict__ bh1,
                            const float* __restrict__ Wh2, const float* __restrict__ bh2,
                            float* __restrict__ out, int nGraphs) {
    __shared__ float sg[D];
    __shared__ float sh1[HID];
    int g = blockIdx.x;
    if (g >= nGraphs) return;
    int tid = threadIdx.x;  // 64 threads
    sg[tid]       = pool[g * D + tid];
    sg[tid + HID] = pool[g * D + tid + HID];
    __syncthreads();
    float a = bh1[tid];
    #pragma unroll 4
    for (int k = 0; k < D; k++) a += sg[k] * Wh1[k * HID + tid];
    sh1[tid] = a > 0.f ? a : 0.f;
    __syncthreads();
    if (tid < NCLS) {
        float o = bh2[tid];
        #pragma unroll
        for (int k = 0; k < HID; k++) o += sh1[k] * Wh2[k * NCLS + tid];
        out[g * NCLS + tid] = 1.f / (1.f + expf(-o));
    }
}

// ---------------- launcher ---------------------------------------------------
extern "C" void kernel_launch(void* const* d_in, const int* in_sizes, int n_in,
                              void* d_out, int out_size) {
    const float* x     = (const float*)d_in[0];
    const int*   ei    = (const int*)d_in[1];
    const int*   batch = (const int*)d_in[2];
    const float* W1    = (const float*)d_in[3];
    const float* b1    = (const float*)d_in[4];
    const float* W2    = (const float*)d_in[5];
    const float* b2    = (const float*)d_in[6];
    const float* bns   = (const float*)d_in[7];
    const float* bnb   = (const float*)d_in[8];
    const float* bnm   = (const float*)d_in[9];
    const float* bnv   = (const float*)d_in[10];
    const float* Wh1   = (const float*)d_in[11];
    const float* bh1   = (const float*)d_in[12];
    const float* Wh2   = (const float*)d_in[13];
    const float* bh2   = (const float*)d_in[14];
    float* out = (float*)d_out;

    int nNodes  = in_sizes[0] / D;
    int nEdges  = in_sizes[1] / 2;
    int nGraphs = out_size / NCLS;

    const int* src = ei;
    const int* dst = ei + nEdges;

    float *h, *x1, *x2, *pool, *w1t, *w2t;
    int *cnt, *rowptr, *tick, *csrsrc;
    cudaGetSymbolAddress((void**)&h,      g_h);
    cudaGetSymbolAddress((void**)&x1,     g_x1);
    cudaGetSymbolAddress((void**)&x2,     g_x2);
    cudaGetSymbolAddress((void**)&pool,   g_pool);
    cudaGetSymbolAddress((void**)&w1t,    g_w1t);
    cudaGetSymbolAddress((void**)&w2t,    g_w2t);
    cudaGetSymbolAddress((void**)&cnt,    g_cnt);
    cudaGetSymbolAddress((void**)&rowptr, g_rowptr);
    cudaGetSymbolAddress((void**)&tick,   g_tick);
    cudaGetSymbolAddress((void**)&csrsrc, g_csrsrc);

    cudaFuncSetAttribute(mlp_mma_kernel, cudaFuncAttributeMaxDynamicSharedMemorySize,
                         SMEM_TOTAL_MLP);

    // weight prep + CSR build (once per launch)
    wprep_kernel<<<dim3(4, 4, 6), dim3(32, 8)>>>(W1, W2, w1t, w2t);
    cudaMemsetAsync(cnt, 0, (size_t)nNodes * sizeof(int));
    int eb = (nEdges + 255) / 256;
    hist_kernel<<<eb, 256>>>(dst, cnt, tick, nEdges);
    scan_kernel<<<1, 1024>>>(cnt, rowptr, nNodes);
    fill_kernel<<<eb, 256>>>(src, dst, rowptr, tick, csrsrc, nEdges);

    cudaMemsetAsync(pool, 0, (size_t)nGraphs * D * sizeof(float));

    int mlpBlocks    = (nNodes + TILE_M - 1) / TILE_M;
    int gatherBlocks = (nNodes * 32 + 255) / 256;
    const float* xs[3] = { x, x1, x2 };
    float*       xd[3] = { x1, x2, x1 };

    for (int l = 0; l < 3; l++) {
        gather_kernel<<<gatherBlocks, 256>>>(xs[l], rowptr, csrsrc, h, nNodes);
        mlp_mma_kernel<<<mlpBlocks, 256, SMEM_TOTAL_MLP>>>(
            h,
            w1t + l * D * D, b1 + l * D,
            w2t + l * D * D, b2 + l * D,
            bns + l * D, bnb + l * D, bnm + l * D, bnv + l * D,
            xd[l], batch, pool, (l == 2) ? 1 : 0, nNodes);
    }

    head_kernel<<<nGraphs, HID>>>(pool, Wh1, bh1, Wh2, bh2, out, nGraphs);
}